// round 17
// baseline (speedup 1.0000x reference)
#include <cuda_runtime.h>
#include <cooperative_groups.h>
#include <math.h>

namespace cg = cooperative_groups;

#define HW 64
#define NP 4096
#define CK 1024
#define MAXB 32

// scratch: [batch][arr(0=g,1=bnd)][4096] — four sorted ascending 1024-chunks per array
__device__ __align__(16) float g_scr[2 * MAXB * NP];
// per-block partial sums + monotonic ticket (never reset; graph-replay-safe)
__device__ float g_part[MAXB * 8];
__device__ unsigned int g_tick;

__global__ __launch_bounds__(1024, 1) __cluster_dims__(8, 1, 1)
void chamfer_kernel(const float* __restrict__ depth,
                    const float* __restrict__ bnd,
                    float* __restrict__ out,
                    float inv_total, int nblk) {
    __shared__ float sm[NP];       // sort: dbuf = sm[0..2047]; query: full 4096 target
    __shared__ float swarp[32];

    cg::cluster_group cluster = cg::this_cluster();
    const int t    = threadIdx.x;
    const int blk  = blockIdx.x;
    const int rank = (int)cluster.block_rank();   // 0..7 (one batch per cluster)
    const int c    = rank & 3;          // chunk quarter
    const int arr  = rank >> 2;         // 0 = sobel(g), 1 = boundary
    const int b    = blk >> 3;          // batch

    // ---- Phase 1: one element per thread ----
    const int e = c * CK + t;
    float v;
    if (arr == 1) {
        v = bnd[b * NP + e];
    } else {
        const float* d = depth + b * NP;
        int y = e >> 6, x = e & 63;
        float p[3][3];
        #pragma unroll
        for (int dy = -1; dy <= 1; dy++)
            #pragma unroll
            for (int dx = -1; dx <= 1; dx++) {
                int yy = y + dy, xx = x + dx;
                bool ok = (yy >= 0) & (yy < HW) & (xx >= 0) & (xx < HW);
                p[dy + 1][dx + 1] = ok ? d[yy * HW + xx] : 0.0f;
            }
        float gx = (p[0][0] - p[0][2]) + 2.0f * (p[1][0] - p[1][2]) + (p[2][0] - p[2][2]);
        float gy = (p[0][0] - p[2][0]) + 2.0f * (p[0][1] - p[2][1]) + (p[0][2] - p[2][2]);
        v = sqrtf(gx * gx + gy * gy + 1e-8f);
    }

    // ---- Phase 2: ascending bitonic sort of 1024 elems, 1 elem/thread ----
    // j<=16: shfl (in-warp). j>=32: double-buffered smem, one __syncthreads per
    // step (j=32 crosses warps — never shfl it; R8/R9 lesson). 15 smem steps.
    int pbuf = 0;
    #pragma unroll
    for (int k = 2; k <= CK; k <<= 1) {
        #pragma unroll
        for (int j = k >> 1; j >= 1; j >>= 1) {
            bool keepMin = ((t & j) == 0) == ((t & k) == 0);
            float o;
            if (j >= 32) {
                float* buf = sm + pbuf * CK;
                buf[t] = v;
                __syncthreads();
                o = buf[t ^ j];
                pbuf ^= 1;
            } else {
                o = __shfl_xor_sync(0xffffffffu, v, j);
            }
            v = keepMin ? fminf(v, o) : fmaxf(v, o);
        }
    }

    // publish sorted chunk to L2 scratch (v stays in register as this thread's
    // query; query multiset unchanged, final sum permutation-invariant)
    g_scr[(b * 2 + arr) * NP + e] = v;

    // ---- Phase 3: cluster barrier (HW; replaces the ticket spin-barrier).
    // Release/acquire at cluster scope orders the g_scr L2 writes; L1 cannot
    // hold stale lines (per-launch L1D flush; first touch after the barrier).
    __syncthreads();        // all smem sort traffic complete before reuse below
    __threadfence();        // belt-and-braces release for the global stores
    cluster.sync();

    // ---- Phase 4: load other array's 4 sorted chunks from L2, search ----
    const float* tgt = g_scr + (b * 2 + (arr ^ 1)) * NP;
    ((float4*)sm)[t] = ((const float4*)tgt)[t];   // 4096 floats via L2
    __syncthreads();

    const float x = v;
    float dmin = 3.4e38f;
    #pragma unroll
    for (int ch = 0; ch < 4; ch++) {
        const float* T = sm + (ch << 10);
        int pos = 0;                  // branchless lower_bound, saturates at CK-1
        #pragma unroll
        for (int s = CK / 2; s >= 1; s >>= 1) {
            if (T[pos + s - 1] < x) pos += s;
        }
        // if x > all elements of chunk: pos=CK-1, T[pos]<x, fabsf = dist to max
        float dd = fabsf(T[pos] - x);
        if (pos > 0) dd = fminf(dd, x - T[pos - 1]);
        dmin = fminf(dmin, dd);
    }
    float acc = dmin;

    // ---- Phase 5: block reduce; ticket finalize (replay-safe, cross-cluster) ----
    #pragma unroll
    for (int o = 16; o > 0; o >>= 1) acc += __shfl_xor_sync(0xffffffffu, acc, o);
    if ((t & 31) == 0) swarp[t >> 5] = acc;
    __syncthreads();
    if (t < 32) {
        float z = swarp[t];           // exactly 32 warps
        #pragma unroll
        for (int o = 16; o > 0; o >>= 1) z += __shfl_xor_sync(0xffffffffu, z, o);
        if (t == 0) {
            g_part[blk] = z;
            __threadfence();
            unsigned int tk = atomicAdd(&g_tick, 1u);
            if ((tk % (unsigned)nblk) == (unsigned)(nblk - 1)) {
                __threadfence();      // all partials of this launch visible
                float s = 0.0f;
                for (int i2 = 0; i2 < nblk; i2++)
                    s += ((volatile float*)g_part)[i2];
                out[0] = s * inv_total;   // overwrites poison on every replay
            }
        }
    }
}

extern "C" void kernel_launch(void* const* d_in, const int* in_sizes, int n_in,
                              void* d_out, int out_size) {
    const float* depth = (const float*)d_in[0];
    const float* bnd   = (const float*)d_in[1];
    float* out = (float*)d_out;

    int B = in_sizes[0] / NP;
    if (B > MAXB) B = MAXB;
    int nblk = B * 8;                 // multiple of cluster size 8
    float inv_total = 1.0f / (float)(B * NP);

    chamfer_kernel<<<nblk, 1024>>>(depth, bnd, out, inv_total, nblk);
}